// round 14
// baseline (speedup 1.0000x reference)
#include <cuda_runtime.h>

// Problem constants (from reference): U=16384, V=50000, P=65536, F=20, D=64, NF=100000
#define DIM 64
#define FMAX 32
#define U_MAX 16384
#define V_MAX 50000

// Scratch (static device globals — allocation-free)
__device__ float  g_xu[(size_t)U_MAX * DIM];   // h2 ⊙ p_ud   [U,64]  (4 MB)
__device__ float  g_qv[(size_t)V_MAX * DIM];   // q_vd        [V,64]  (12.8 MB)
__device__ float  g_su[U_MAX];                 // user scalar
__device__ float  g_sv[V_MAX];                 // item scalar
__device__ float  g_A[DIM * DIM];              // Xu^T Xu  (h2-weighted user Gram)
__device__ float  g_B[DIM * DIM];              // Qv^T Qv
__device__ double g_pos;                       // positive-pair loss accumulator

// ---------------------------------------------------------------------------
// Zero the accumulators (must run every launch — graph replays reuse state)
// ---------------------------------------------------------------------------
__global__ void zero_kernel() {
    int t = blockIdx.x * blockDim.x + threadIdx.x;
    if (t < DIM * DIM) { g_A[t] = 0.0f; g_B[t] = 0.0f; }
    if (t == 0) g_pos = 0.0;
}

// ---------------------------------------------------------------------------
// Entity kernel: one block (64 threads) per entity.
//   s_d   = sum_f emb[idx_f, d]
//   bi_d  = 0.5 (s_d^2 - sum_f emb^2)
//   scal  = bi . h1 + sum_f w[idx_f] + extra
//   USER:  x[n,d] = h2[d] * s_d      ITEM:  q[n,d] = s_d
// ---------------------------------------------------------------------------
template <bool USER>
__global__ void entity_kernel(const float* __restrict__ emb,
                              const float* __restrict__ w,
                              const int*   __restrict__ fidx,
                              const float* __restrict__ h1,
                              const float* __restrict__ h2,
                              const float* __restrict__ bias,
                              int N, int F) {
    int n = blockIdx.x;
    if (n >= N) return;
    int d = threadIdx.x;            // 0..63

    __shared__ int   sidx[FMAX];
    __shared__ float sred[2];

    if (d < F) sidx[d] = fidx[n * F + d];
    __syncthreads();

    float s = 0.0f, ss = 0.0f;
    for (int f = 0; f < F; ++f) {
        float v = emb[sidx[f] * DIM + d];
        s  += v;
        ss += v * v;
    }

    float bi = 0.5f * (s * s - ss);
    float partial = bi * h1[d];
    if (d < F) partial += w[sidx[d]];          // fold linear term into reduction

    if (USER) g_xu[n * DIM + d] = h2[d] * s;
    else      g_qv[n * DIM + d] = s;

    // reduce partial over 64 threads (2 warps)
    #pragma unroll
    for (int o = 16; o; o >>= 1)
        partial += __shfl_down_sync(0xffffffffu, partial, o);
    if ((d & 31) == 0) sred[d >> 5] = partial;
    __syncthreads();
    if (d == 0) {
        float tot = sred[0] + sred[1] + (USER ? bias[0] : 0.0f);
        if (USER) g_su[n] = tot;
        else      g_sv[n] = tot;
    }
}

// ---------------------------------------------------------------------------
// Gram kernel: C = X^T X for X [N,64].  256 threads/block.
// thread t: j = t&63, ib = t>>6; owns 16 rows i = ib + 4k. Tiles of 32 rows in smem.
// ---------------------------------------------------------------------------
template <bool USER>
__global__ void gram_kernel(int N) {
    const float* __restrict__ X = USER ? g_xu : g_qv;
    float*       __restrict__ C = USER ? g_A  : g_B;

    __shared__ float xs[32][DIM];
    int t  = threadIdx.x;
    int j  = t & 63;
    int ib = t >> 6;                 // 0..3, uniform per warp (broadcast smem reads)

    float acc[16];
    #pragma unroll
    for (int k = 0; k < 16; ++k) acc[k] = 0.0f;

    int ntiles = (N + 31) >> 5;
    for (int tile = blockIdx.x; tile < ntiles; tile += gridDim.x) {
        int base = tile << 5;
        __syncthreads();             // protect previous tile reads
        #pragma unroll
        for (int r = 0; r < 8; ++r) {
            int e = t + r * 256;
            int row = e >> 6, col = e & 63;
            int g = base + row;
            xs[row][col] = (g < N) ? X[g * DIM + col] : 0.0f;
        }
        __syncthreads();

        #pragma unroll 4
        for (int u = 0; u < 32; ++u) {
            float xj = xs[u][j];
            #pragma unroll
            for (int k = 0; k < 16; ++k)
                acc[k] += xs[u][ib + 4 * k] * xj;
        }
    }

    #pragma unroll
    for (int k = 0; k < 16; ++k)
        atomicAdd(&C[(ib + 4 * k) * DIM + j], acc[k]);
}

// ---------------------------------------------------------------------------
// Positive pairs: one warp per pair (grid-stride).
//   y = dot(xu[u], qv[v]) + su[u] + sv[v];  loss += 0.5 y^2 - 2 y
// ---------------------------------------------------------------------------
__global__ void pos_kernel(const int* __restrict__ uid,
                           const int* __restrict__ vid, int P) {
    int wid  = (blockIdx.x * blockDim.x + threadIdx.x) >> 5;
    int lane = threadIdx.x & 31;
    int nw   = (gridDim.x * blockDim.x) >> 5;

    double local = 0.0;
    for (int p = wid; p < P; p += nw) {
        int u = uid[p], v = vid[p];
        const float* xp = g_xu + u * DIM;
        const float* qp = g_qv + v * DIM;
        float dot = xp[lane] * qp[lane] + xp[lane + 32] * qp[lane + 32];
        #pragma unroll
        for (int o = 16; o; o >>= 1)
            dot += __shfl_down_sync(0xffffffffu, dot, o);
        if (lane == 0) {
            double y = (double)(dot + g_su[u] + g_sv[v]);
            local += 0.5 * y * y - 2.0 * y;
        }
    }
    if (lane == 0) atomicAdd(&g_pos, local);
}

// ---------------------------------------------------------------------------
// Final: out = 0.5 * sum(A .* B) + pos
// ---------------------------------------------------------------------------
__global__ void final_kernel(float* __restrict__ out) {
    __shared__ double sred[8];
    int t = threadIdx.x;
    double local = 0.0;
    for (int i = t; i < DIM * DIM; i += 256)
        local += (double)g_A[i] * (double)g_B[i];
    #pragma unroll
    for (int o = 16; o; o >>= 1)
        local += __shfl_down_sync(0xffffffffu, local, o);
    if ((t & 31) == 0) sred[t >> 5] = local;
    __syncthreads();
    if (t == 0) {
        double s = 0.0;
        #pragma unroll
        for (int w = 0; w < 8; ++w) s += sred[w];
        out[0] = (float)(0.5 * s + g_pos);
    }
}

// ---------------------------------------------------------------------------
extern "C" void kernel_launch(void* const* d_in, const int* in_sizes, int n_in,
                              void* d_out, int out_size) {
    const float* user_emb      = (const float*)d_in[0];
    const float* item_emb      = (const float*)d_in[1];
    const float* w_user        = (const float*)d_in[2];
    const float* w_item        = (const float*)d_in[3];
    const float* bias          = (const float*)d_in[4];
    const float* h1            = (const float*)d_in[5];
    const float* h2            = (const float*)d_in[6];
    const int*   user_feat_idx = (const int*)d_in[7];
    const int*   item_feat_idx = (const int*)d_in[8];
    const int*   pos_user_ids  = (const int*)d_in[9];
    const int*   pos_item_ids  = (const int*)d_in[10];

    const int F = 20;
    int U = in_sizes[7] / F;
    int V = in_sizes[8] / F;
    int P = in_sizes[9];

    zero_kernel<<<(DIM * DIM + 255) / 256, 256>>>();

    entity_kernel<true ><<<U, DIM>>>(user_emb, w_user, user_feat_idx, h1, h2, bias, U, F);
    entity_kernel<false><<<V, DIM>>>(item_emb, w_item, item_feat_idx, h1, h2, bias, V, F);

    gram_kernel<true ><<<296, 256>>>(U);
    gram_kernel<false><<<296, 256>>>(V);

    pos_kernel<<<256, 256>>>(pos_user_ids, pos_item_ids, P);

    final_kernel<<<1, 256>>>((float*)d_out);
}

// round 15
// speedup vs baseline: 1.0016x; 1.0016x over previous
#include <cuda_runtime.h>

// Problem constants (from reference): U=16384, V=50000, P=65536, F=20, D=64, NF=100000
#define DIM 64
#define FMAX 32
#define U_MAX 16384
#define V_MAX 50000

// Scratch (static device globals — allocation-free)
__device__ float  g_xu[(size_t)U_MAX * DIM];   // h2 ⊙ p_ud   [U,64]  (4 MB)
__device__ float  g_qv[(size_t)V_MAX * DIM];   // q_vd        [V,64]  (12.8 MB)
__device__ float  g_su[U_MAX];                 // user scalar
__device__ float  g_sv[V_MAX];                 // item scalar
__device__ float  g_A[DIM * DIM];              // Xu^T Xu  (h2-weighted user Gram)
__device__ float  g_B[DIM * DIM];              // Qv^T Qv
__device__ double g_pos;                       // positive-pair loss accumulator

// ---------------------------------------------------------------------------
// Zero the accumulators (must run every launch — graph replays reuse state)
// ---------------------------------------------------------------------------
__global__ void zero_kernel() {
    int t = blockIdx.x * blockDim.x + threadIdx.x;
    if (t < DIM * DIM) { g_A[t] = 0.0f; g_B[t] = 0.0f; }
    if (t == 0) g_pos = 0.0;
}

// ---------------------------------------------------------------------------
// Entity kernel: one block (64 threads) per entity.
//   s_d   = sum_f emb[idx_f, d]
//   bi_d  = 0.5 (s_d^2 - sum_f emb^2)
//   scal  = bi . h1 + sum_f w[idx_f] + extra
//   USER:  x[n,d] = h2[d] * s_d      ITEM:  q[n,d] = s_d
// ---------------------------------------------------------------------------
template <bool USER>
__global__ void entity_kernel(const float* __restrict__ emb,
                              const float* __restrict__ w,
                              const int*   __restrict__ fidx,
                              const float* __restrict__ h1,
                              const float* __restrict__ h2,
                              const float* __restrict__ bias,
                              int N, int F) {
    int n = blockIdx.x;
    if (n >= N) return;
    int d = threadIdx.x;            // 0..63

    __shared__ int   sidx[FMAX];
    __shared__ float sred[2];

    if (d < F) sidx[d] = fidx[n * F + d];
    __syncthreads();

    float s = 0.0f, ss = 0.0f;
    for (int f = 0; f < F; ++f) {
        float v = emb[sidx[f] * DIM + d];
        s  += v;
        ss += v * v;
    }

    float bi = 0.5f * (s * s - ss);
    float partial = bi * h1[d];
    if (d < F) partial += w[sidx[d]];          // fold linear term into reduction

    if (USER) g_xu[n * DIM + d] = h2[d] * s;
    else      g_qv[n * DIM + d] = s;

    // reduce partial over 64 threads (2 warps)
    #pragma unroll
    for (int o = 16; o; o >>= 1)
        partial += __shfl_down_sync(0xffffffffu, partial, o);
    if ((d & 31) == 0) sred[d >> 5] = partial;
    __syncthreads();
    if (d == 0) {
        float tot = sred[0] + sred[1] + (USER ? bias[0] : 0.0f);
        if (USER) g_su[n] = tot;
        else      g_sv[n] = tot;
    }
}

// ---------------------------------------------------------------------------
// Gram kernel: C = X^T X for X [N,64].  256 threads/block.
// thread t: j = t&63, ib = t>>6; owns 16 rows i = ib + 4k. Tiles of 32 rows in smem.
// ---------------------------------------------------------------------------
template <bool USER>
__global__ void gram_kernel(int N) {
    const float* __restrict__ X = USER ? g_xu : g_qv;
    float*       __restrict__ C = USER ? g_A  : g_B;

    __shared__ float xs[32][DIM];
    int t  = threadIdx.x;
    int j  = t & 63;
    int ib = t >> 6;                 // 0..3, uniform per warp (broadcast smem reads)

    float acc[16];
    #pragma unroll
    for (int k = 0; k < 16; ++k) acc[k] = 0.0f;

    int ntiles = (N + 31) >> 5;
    for (int tile = blockIdx.x; tile < ntiles; tile += gridDim.x) {
        int base = tile << 5;
        __syncthreads();             // protect previous tile reads
        #pragma unroll
        for (int r = 0; r < 8; ++r) {
            int e = t + r * 256;
            int row = e >> 6, col = e & 63;
            int g = base + row;
            xs[row][col] = (g < N) ? X[g * DIM + col] : 0.0f;
        }
        __syncthreads();

        #pragma unroll 4
        for (int u = 0; u < 32; ++u) {
            float xj = xs[u][j];
            #pragma unroll
            for (int k = 0; k < 16; ++k)
                acc[k] += xs[u][ib + 4 * k] * xj;
        }
    }

    #pragma unroll
    for (int k = 0; k < 16; ++k)
        atomicAdd(&C[(ib + 4 * k) * DIM + j], acc[k]);
}

// ---------------------------------------------------------------------------
// Positive pairs: one warp per pair (grid-stride).
//   y = dot(xu[u], qv[v]) + su[u] + sv[v];  loss += 0.5 y^2 - 2 y
// ---------------------------------------------------------------------------
__global__ void pos_kernel(const int* __restrict__ uid,
                           const int* __restrict__ vid, int P) {
    int wid  = (blockIdx.x * blockDim.x + threadIdx.x) >> 5;
    int lane = threadIdx.x & 31;
    int nw   = (gridDim.x * blockDim.x) >> 5;

    double local = 0.0;
    for (int p = wid; p < P; p += nw) {
        int u = uid[p], v = vid[p];
        const float* xp = g_xu + u * DIM;
        const float* qp = g_qv + v * DIM;
        float dot = xp[lane] * qp[lane] + xp[lane + 32] * qp[lane + 32];
        #pragma unroll
        for (int o = 16; o; o >>= 1)
            dot += __shfl_down_sync(0xffffffffu, dot, o);
        if (lane == 0) {
            double y = (double)(dot + g_su[u] + g_sv[v]);
            local += 0.5 * y * y - 2.0 * y;
        }
    }
    if (lane == 0) atomicAdd(&g_pos, local);
}

// ---------------------------------------------------------------------------
// Final: out = 0.5 * sum(A .* B) + pos
// ---------------------------------------------------------------------------
__global__ void final_kernel(float* __restrict__ out) {
    __shared__ double sred[8];
    int t = threadIdx.x;
    double local = 0.0;
    for (int i = t; i < DIM * DIM; i += 256)
        local += (double)g_A[i] * (double)g_B[i];
    #pragma unroll
    for (int o = 16; o; o >>= 1)
        local += __shfl_down_sync(0xffffffffu, local, o);
    if ((t & 31) == 0) sred[t >> 5] = local;
    __syncthreads();
    if (t == 0) {
        double s = 0.0;
        #pragma unroll
        for (int w = 0; w < 8; ++w) s += sred[w];
        out[0] = (float)(0.5 * s + g_pos);
    }
}

// ---------------------------------------------------------------------------
extern "C" void kernel_launch(void* const* d_in, const int* in_sizes, int n_in,
                              void* d_out, int out_size) {
    const float* user_emb      = (const float*)d_in[0];
    const float* item_emb      = (const float*)d_in[1];
    const float* w_user        = (const float*)d_in[2];
    const float* w_item        = (const float*)d_in[3];
    const float* bias          = (const float*)d_in[4];
    const float* h1            = (const float*)d_in[5];
    const float* h2            = (const float*)d_in[6];
    const int*   user_feat_idx = (const int*)d_in[7];
    const int*   item_feat_idx = (const int*)d_in[8];
    const int*   pos_user_ids  = (const int*)d_in[9];
    const int*   pos_item_ids  = (const int*)d_in[10];

    const int F = 20;
    int U = in_sizes[7] / F;
    int V = in_sizes[8] / F;
    int P = in_sizes[9];

    zero_kernel<<<(DIM * DIM + 255) / 256, 256>>>();

    entity_kernel<true ><<<U, DIM>>>(user_emb, w_user, user_feat_idx, h1, h2, bias, U, F);
    entity_kernel<false><<<V, DIM>>>(item_emb, w_item, item_feat_idx, h1, h2, bias, V, F);

    gram_kernel<true ><<<296, 256>>>(U);
    gram_kernel<false><<<296, 256>>>(V);

    pos_kernel<<<256, 256>>>(pos_user_ids, pos_item_ids, P);

    final_kernel<<<1, 256>>>((float*)d_out);
}